// round 1
// baseline (speedup 1.0000x reference)
#include <cuda_runtime.h>
#include <math.h>

// Problem constants
#define CTRLN 256
#define WORDN 128
#define MEMN  128
#define DINN  64
#define BN    512
#define TN    512
#define GINN  192            // D_IN + WORD
#define EPSF  1e-6f

// ---------------- device scratch (static, no allocs) ----------------
__device__ float g_WtIH[48 * 768 * 4];        // [k4][o(768)][p]  k = 4*k4+p, gi weights
__device__ float g_WtHH[64 * 768 * 4];        // [k4][o(768)][p]  gh weights
__device__ float g_WtHD[64 * 512 * 4];        // [k4][o(512)][p]  head: key|erase|add|beta|pad
__device__ float g_M[(size_t)BN * MEMN * WORDN];  // 32MB memory state

// ---------------- helpers ----------------
__device__ __forceinline__ void ffma2(float2 &d, float2 a, float2 b) {
    unsigned long long &du = reinterpret_cast<unsigned long long &>(d);
    unsigned long long au = reinterpret_cast<unsigned long long &>(a);
    unsigned long long bu = reinterpret_cast<unsigned long long &>(b);
    asm("fma.rn.f32x2 %0, %1, %2, %0;" : "+l"(du) : "l"(au), "l"(bu));
}
__device__ __forceinline__ float2 dup2(float a) { return make_float2(a, a); }
__device__ __forceinline__ float sigf(float x) { return 1.0f / (1.0f + __expf(-x)); }
__device__ __forceinline__ float softplusf(float x) {
    return fmaxf(x, 0.0f) + log1pf(__expf(-fabsf(x)));
}

// ---------------- K0: weight repack ----------------
__global__ void ntm_prep(const float* __restrict__ W_ih, const float* __restrict__ W_hh,
                         const float* __restrict__ W_key, const float* __restrict__ W_beta,
                         const float* __restrict__ W_erase, const float* __restrict__ W_add) {
    int stride = gridDim.x * blockDim.x;
    int idx0 = blockIdx.x * blockDim.x + threadIdx.x;
    // W_ih [768,192] -> g_WtIH[(k>>2)*3072 + o*4 + (k&3)]
    for (int i = idx0; i < 768 * 192; i += stride) {
        int o = i / 192, k = i % 192;
        g_WtIH[(k >> 2) * (768 * 4) + o * 4 + (k & 3)] = W_ih[i];
    }
    // W_hh [768,256]
    for (int i = idx0; i < 768 * 256; i += stride) {
        int o = i / 256, k = i % 256;
        g_WtHH[(k >> 2) * (768 * 4) + o * 4 + (k & 3)] = W_hh[i];
    }
    // head combined: columns 0-127 key, 128-255 erase, 256-383 add, 384 beta, 385-511 zero
    for (int i = idx0; i < 64 * 512 * 4; i += stride) {
        int k4 = i / (512 * 4);
        int r = i % (512 * 4);
        int o = r >> 2, p = r & 3;
        int k = k4 * 4 + p;
        float v = 0.0f;
        if (o < 128)       v = W_key[o * 256 + k];
        else if (o < 256)  v = W_erase[(o - 128) * 256 + k];
        else if (o < 384)  v = W_add[(o - 256) * 256 + k];
        else if (o == 384) v = W_beta[k];
        g_WtHD[i] = v;
    }
}

// ---------------- K1: persistent main kernel (1 CTA = 4 batch elems, all T steps) ----------------
__global__ __launch_bounds__(256, 1)
void ntm_main(const float* __restrict__ data, const int* __restrict__ batch_sizes,
              const int* __restrict__ unsort_idxs,
              const float* __restrict__ b_ih, const float* __restrict__ b_hh,
              const float* __restrict__ b_key, const float* __restrict__ b_beta,
              const float* __restrict__ b_erase, const float* __restrict__ b_add,
              const float* __restrict__ M0, float* __restrict__ out) {
    __shared__ __align__(16) float s_in[GINN][4];     // GRU input [k][elem]: rows 0..63 x_t, 64..191 read
    __shared__ __align__(16) float s_h[CTRLN][4];     // ctrl state [k][elem]
    __shared__ __align__(16) float s_key[4][WORDN];   // normalized key
    __shared__ __align__(16) float s_e[4][WORDN];     // erase (sigmoid)
    __shared__ __align__(16) float s_a[4][WORDN];     // add
    __shared__ __align__(16) float s_w[4][MEMN];      // cos -> softmax weights
    __shared__ __align__(16) float s_racc[4][2][WORDN];
    __shared__ float s_beta[4];
    __shared__ int s_len[4];
    __shared__ int s_dst[4];

    const int tid = threadIdx.x;
    const int lane = tid & 31;
    const int warp = tid >> 5;
    const int b0 = blockIdx.x * 4;
    const int j = tid;  // GRU gate index / head thread index

    // ---- active lengths L_e = #{t : batch_sizes[t] > b0+e} ----
    if (warp < 4) {
        int e = warp, cnt = 0;
        for (int t = lane; t < TN; t += 32) cnt += (batch_sizes[t] > (b0 + e)) ? 1 : 0;
        #pragma unroll
        for (int s = 16; s; s >>= 1) cnt += __shfl_xor_sync(0xffffffffu, cnt, s);
        if (lane == 0) s_len[e] = cnt;
    }
    // ---- init M from M0 for 4 elems ----
    for (int i = tid; i < (MEMN * WORDN) / 4; i += 256) {
        float4 v = ((const float4*)M0)[i];
        #pragma unroll
        for (int e = 0; e < 4; e++)
            ((float4*)g_M)[(size_t)(b0 + e) * ((MEMN * WORDN) / 4) + i] = v;
    }
    // ---- init states ----
    for (int i = tid; i < GINN * 4; i += 256) (&s_in[0][0])[i] = 0.0f;
    for (int i = tid; i < CTRLN * 4; i += 256) (&s_h[0][0])[i] = 0.0f;
    __syncthreads();

    const int L0 = s_len[0], L1 = s_len[1], L2 = s_len[2], L3 = s_len[3];
    const int Tmax = max(max(L0, L1), max(L2, L3));

    // ---- biases hoisted to registers ----
    const float bR  = b_ih[j] + b_hh[j];
    const float bZ  = b_ih[256 + j] + b_hh[256 + j];
    const float bNi = b_ih[512 + j];
    const float bNh = b_hh[512 + j];
    const float bH1 = (j < 128) ? b_key[j] : b_erase[j - 128];
    const float bH2 = (j < 128) ? b_add[j] : ((j == 128) ? b_beta[0] : 0.0f);

    for (int t = 0; t < Tmax; ++t) {
        // ---- load x_t for 4 elems into s_in rows 0..63 ----
        {
            int e = tid >> 6, d = tid & 63;
            s_in[d][e] = data[((size_t)t * BN + (b0 + e)) * DINN + d];
        }
        __syncthreads();

        // ================= GRU GEMM (f32x2 over elem pairs) =================
        float2 ar0 = dup2(bR), ar1 = dup2(bR);
        float2 az0 = dup2(bZ), az1 = dup2(bZ);
        float2 ai0 = dup2(bNi), ai1 = dup2(bNi);
        float2 ah0 = dup2(bNh), ah1 = dup2(bNh);
        {   // gi: k over 192 (input = x ++ read)
            const float4* W = (const float4*)g_WtIH;
            #pragma unroll 4
            for (int k4 = 0; k4 < 48; ++k4) {
                float4 wr = __ldg(&W[k4 * 768 + j]);
                float4 wz = __ldg(&W[k4 * 768 + 256 + j]);
                float4 wn = __ldg(&W[k4 * 768 + 512 + j]);
                #pragma unroll
                for (int p = 0; p < 4; p++) {
                    float4 iv = *(const float4*)&s_in[k4 * 4 + p][0];
                    float2 i0 = make_float2(iv.x, iv.y);
                    float2 i1 = make_float2(iv.z, iv.w);
                    float wrp = (p == 0) ? wr.x : (p == 1) ? wr.y : (p == 2) ? wr.z : wr.w;
                    float wzp = (p == 0) ? wz.x : (p == 1) ? wz.y : (p == 2) ? wz.z : wz.w;
                    float wnp = (p == 0) ? wn.x : (p == 1) ? wn.y : (p == 2) ? wn.z : wn.w;
                    float2 wd;
                    wd = dup2(wrp); ffma2(ar0, wd, i0); ffma2(ar1, wd, i1);
                    wd = dup2(wzp); ffma2(az0, wd, i0); ffma2(az1, wd, i1);
                    wd = dup2(wnp); ffma2(ai0, wd, i0); ffma2(ai1, wd, i1);
                }
            }
        }
        {   // gh: k over 256 (input = ctrl)
            const float4* W = (const float4*)g_WtHH;
            #pragma unroll 4
            for (int k4 = 0; k4 < 64; ++k4) {
                float4 wr = __ldg(&W[k4 * 768 + j]);
                float4 wz = __ldg(&W[k4 * 768 + 256 + j]);
                float4 wn = __ldg(&W[k4 * 768 + 512 + j]);
                #pragma unroll
                for (int p = 0; p < 4; p++) {
                    float4 iv = *(const float4*)&s_h[k4 * 4 + p][0];
                    float2 i0 = make_float2(iv.x, iv.y);
                    float2 i1 = make_float2(iv.z, iv.w);
                    float wrp = (p == 0) ? wr.x : (p == 1) ? wr.y : (p == 2) ? wr.z : wr.w;
                    float wzp = (p == 0) ? wz.x : (p == 1) ? wz.y : (p == 2) ? wz.z : wz.w;
                    float wnp = (p == 0) ? wn.x : (p == 1) ? wn.y : (p == 2) ? wn.z : wn.w;
                    float2 wd;
                    wd = dup2(wrp); ffma2(ar0, wd, i0); ffma2(ar1, wd, i1);
                    wd = dup2(wzp); ffma2(az0, wd, i0); ffma2(az1, wd, i1);
                    wd = dup2(wnp); ffma2(ah0, wd, i0); ffma2(ah1, wd, i1);
                }
            }
        }
        // ---- gates (thread j handles gate index j for all 4 elems) ----
        float hn[4];
        {
            float4 hold = *(const float4*)&s_h[j][0];
            float pr[4] = {ar0.x, ar0.y, ar1.x, ar1.y};
            float pz[4] = {az0.x, az0.y, az1.x, az1.y};
            float pi[4] = {ai0.x, ai0.y, ai1.x, ai1.y};
            float ph[4] = {ah0.x, ah0.y, ah1.x, ah1.y};
            float ho[4] = {hold.x, hold.y, hold.z, hold.w};
            #pragma unroll
            for (int e = 0; e < 4; e++) {
                float r = sigf(pr[e]);
                float z = sigf(pz[e]);
                float n = tanhf(pi[e] + r * ph[e]);
                hn[e] = (1.0f - z) * n + z * ho[e];
            }
        }
        __syncthreads();   // all reads of old s_h done
        if (t < L0) s_h[j][0] = hn[0];
        if (t < L1) s_h[j][1] = hn[1];
        if (t < L2) s_h[j][2] = hn[2];
        if (t < L3) s_h[j][3] = hn[3];
        __syncthreads();

        // ================= head GEMM: outputs o1=j (key|erase), o2=256+j (add|beta) =================
        float2 h10 = dup2(bH1), h11 = dup2(bH1);
        float2 h20 = dup2(bH2), h21 = dup2(bH2);
        {
            const float4* W = (const float4*)g_WtHD;
            #pragma unroll 4
            for (int k4 = 0; k4 < 64; ++k4) {
                float4 w1 = __ldg(&W[k4 * 512 + j]);
                float4 w2 = __ldg(&W[k4 * 512 + 256 + j]);
                #pragma unroll
                for (int p = 0; p < 4; p++) {
                    float4 iv = *(const float4*)&s_h[k4 * 4 + p][0];
                    float2 i0 = make_float2(iv.x, iv.y);
                    float2 i1 = make_float2(iv.z, iv.w);
                    float w1p = (p == 0) ? w1.x : (p == 1) ? w1.y : (p == 2) ? w1.z : w1.w;
                    float w2p = (p == 0) ? w2.x : (p == 1) ? w2.y : (p == 2) ? w2.z : w2.w;
                    float2 wd;
                    wd = dup2(w1p); ffma2(h10, wd, i0); ffma2(h11, wd, i1);
                    wd = dup2(w2p); ffma2(h20, wd, i0); ffma2(h21, wd, i1);
                }
            }
        }
        {
            float v1[4] = {h10.x, h10.y, h11.x, h11.y};
            float v2[4] = {h20.x, h20.y, h21.x, h21.y};
            #pragma unroll
            for (int e = 0; e < 4; e++) {
                if (j < 128) {
                    s_key[e][j] = tanhf(v1[e]);   // raw key (normalized below)
                    s_a[e][j] = v2[e];
                } else {
                    s_e[e][j - 128] = sigf(v1[e]);
                    if (j == 128) s_beta[e] = softplusf(v2[e]);
                }
            }
        }
        __syncthreads();

        // ---- normalize key: kn = k/(||k||+eps), one warp per elem ----
        if (warp < 4) {
            int e = warp;
            float4 kv = *(const float4*)&s_key[e][lane * 4];
            float ss = kv.x * kv.x + kv.y * kv.y + kv.z * kv.z + kv.w * kv.w;
            #pragma unroll
            for (int s = 16; s; s >>= 1) ss += __shfl_xor_sync(0xffffffffu, ss, s);
            float inv = 1.0f / (sqrtf(ss) + EPSF);
            kv.x *= inv; kv.y *= inv; kv.z *= inv; kv.w *= inv;
            *(float4*)&s_key[e][lane * 4] = kv;
        }
        __syncthreads();

        // ================= pass 1: cos_m = (M_m . kn)/(||M_m||+eps), 2 warps/elem =================
        {
            int e = warp >> 1, half = warp & 1;
            int Le = s_len[e];
            if (t < Le) {
                const float* Me = g_M + (size_t)(b0 + e) * (MEMN * WORDN);
                int rl = lane >> 3;          // 4 rows per warp-iter
                int cc = (lane & 7) * 16;    // 16 floats per lane
                float4 k0 = *(const float4*)&s_key[e][cc];
                float4 k1 = *(const float4*)&s_key[e][cc + 4];
                float4 k2 = *(const float4*)&s_key[e][cc + 8];
                float4 k3 = *(const float4*)&s_key[e][cc + 12];
                for (int mb = half * 64; mb < half * 64 + 64; mb += 4) {
                    int m = mb + rl;
                    const float4* Mr = (const float4*)(Me + m * WORDN + cc);
                    float4 a0 = Mr[0], a1 = Mr[1], a2 = Mr[2], a3 = Mr[3];
                    float dot = a0.x * k0.x + a0.y * k0.y + a0.z * k0.z + a0.w * k0.w
                              + a1.x * k1.x + a1.y * k1.y + a1.z * k1.z + a1.w * k1.w
                              + a2.x * k2.x + a2.y * k2.y + a2.z * k2.z + a2.w * k2.w
                              + a3.x * k3.x + a3.y * k3.y + a3.z * k3.z + a3.w * k3.w;
                    float nrm = a0.x * a0.x + a0.y * a0.y + a0.z * a0.z + a0.w * a0.w
                              + a1.x * a1.x + a1.y * a1.y + a1.z * a1.z + a1.w * a1.w
                              + a2.x * a2.x + a2.y * a2.y + a2.z * a2.z + a2.w * a2.w
                              + a3.x * a3.x + a3.y * a3.y + a3.z * a3.z + a3.w * a3.w;
                    #pragma unroll
                    for (int s = 1; s < 8; s <<= 1) {
                        dot += __shfl_xor_sync(0xffffffffu, dot, s);
                        nrm += __shfl_xor_sync(0xffffffffu, nrm, s);
                    }
                    if ((lane & 7) == 0) s_w[e][m] = dot / (sqrtf(nrm) + EPSF);
                }
            }
        }
        __syncthreads();

        // ---- softmax over MEM (beta*cos), one warp per elem ----
        if (warp < 4 && t < s_len[warp]) {
            int e = warp;
            float beta = s_beta[e];
            float v0 = beta * s_w[e][lane];
            float v1 = beta * s_w[e][lane + 32];
            float v2 = beta * s_w[e][lane + 64];
            float v3 = beta * s_w[e][lane + 96];
            float mx = fmaxf(fmaxf(v0, v1), fmaxf(v2, v3));
            #pragma unroll
            for (int s = 16; s; s >>= 1) mx = fmaxf(mx, __shfl_xor_sync(0xffffffffu, mx, s));
            v0 = __expf(v0 - mx); v1 = __expf(v1 - mx);
            v2 = __expf(v2 - mx); v3 = __expf(v3 - mx);
            float sum = v0 + v1 + v2 + v3;
            #pragma unroll
            for (int s = 16; s; s >>= 1) sum += __shfl_xor_sync(0xffffffffu, sum, s);
            float inv = 1.0f / sum;
            s_w[e][lane] = v0 * inv;
            s_w[e][lane + 32] = v1 * inv;
            s_w[e][lane + 64] = v2 * inv;
            s_w[e][lane + 96] = v3 * inv;
        }
        __syncthreads();

        // ================= pass 2: read + M update, 2 warps/elem, lane -> cols 4l..4l+3 =================
        {
            int e = warp >> 1, half = warp & 1;
            int Le = s_len[e];
            if (t < Le) {
                float* Me = g_M + (size_t)(b0 + e) * (MEMN * WORDN);
                float4 e4 = *(const float4*)&s_e[e][lane * 4];
                float4 a4 = *(const float4*)&s_a[e][lane * 4];
                float4 racc = make_float4(0.f, 0.f, 0.f, 0.f);
                for (int m = half * 64; m < half * 64 + 64; ++m) {
                    float wm = s_w[e][m];
                    float4* Mr = (float4*)(Me + m * WORDN + lane * 4);
                    float4 mv = *Mr;
                    racc.x = fmaf(wm, mv.x, racc.x);
                    racc.y = fmaf(wm, mv.y, racc.y);
                    racc.z = fmaf(wm, mv.z, racc.z);
                    racc.w = fmaf(wm, mv.w, racc.w);
                    float4 f, nv;
                    f.x = fmaf(-wm, e4.x, 1.0f);
                    f.y = fmaf(-wm, e4.y, 1.0f);
                    f.z = fmaf(-wm, e4.z, 1.0f);
                    f.w = fmaf(-wm, e4.w, 1.0f);
                    nv.x = fmaf(mv.x, f.x, wm * a4.x);
                    nv.y = fmaf(mv.y, f.y, wm * a4.y);
                    nv.z = fmaf(mv.z, f.z, wm * a4.z);
                    nv.w = fmaf(mv.w, f.w, wm * a4.w);
                    *Mr = nv;
                }
                *(float4*)&s_racc[e][half][lane * 4] = racc;
            }
        }
        __syncthreads();
        // combine read halves -> s_in rows 64..191 (only for active elems)
        for (int idx = tid; idx < 512; idx += 256) {
            int e = idx >> 7, w = idx & 127;
            if (t < s_len[e]) s_in[64 + w][e] = s_racc[e][0][w] + s_racc[e][1][w];
        }
        __syncthreads();
    }

    // ---- epilogue: inverse permutation + output ----
    for (int q = tid; q < BN; q += 256) {
        int u = unsort_idxs[q];
        if (u >= b0 && u < b0 + 4) s_dst[u - b0] = q;
    }
    __syncthreads();
    #pragma unroll
    for (int e = 0; e < 4; e++) {
        out[(size_t)s_dst[e] * CTRLN + tid] = s_h[tid][e];
    }
    for (int idx = tid; idx < 512; idx += 256) {
        int e = idx >> 7, w = idx & 127;
        out[(size_t)BN * CTRLN + (size_t)s_dst[e] * WORDN + w] = s_in[64 + w][e];
    }
}

// ---------------- launch ----------------
extern "C" void kernel_launch(void* const* d_in, const int* in_sizes, int n_in,
                              void* d_out, int out_size) {
    const float* data        = (const float*)d_in[0];
    const int*   batch_sizes = (const int*)d_in[1];
    const int*   unsort      = (const int*)d_in[2];
    const float* W_ih        = (const float*)d_in[3];
    const float* b_ih        = (const float*)d_in[4];
    const float* W_hh        = (const float*)d_in[5];
    const float* b_hh        = (const float*)d_in[6];
    const float* W_key       = (const float*)d_in[7];
    const float* b_key       = (const float*)d_in[8];
    const float* W_beta      = (const float*)d_in[9];
    const float* b_beta      = (const float*)d_in[10];
    const float* W_erase     = (const float*)d_in[11];
    const float* b_erase     = (const float*)d_in[12];
    const float* W_add       = (const float*)d_in[13];
    const float* b_add       = (const float*)d_in[14];
    const float* M0          = (const float*)d_in[15];

    ntm_prep<<<256, 256>>>(W_ih, W_hh, W_key, W_beta, W_erase, W_add);
    ntm_main<<<128, 256>>>(data, batch_sizes, unsort,
                           b_ih, b_hh, b_key, b_beta, b_erase, b_add,
                           M0, (float*)d_out);
}

// round 2
// speedup vs baseline: 1.3108x; 1.3108x over previous
#include <cuda_runtime.h>
#include <cuda_fp16.h>
#include <math.h>

// Problem constants
#define CTRLN 256
#define WORDN 128
#define MEMN  128
#define DINN  64
#define BN    512
#define TN    512
#define GINN  192            // D_IN + WORD
#define EPSF  1e-6f

// ---------------- device scratch (static, no allocs) ----------------
__device__ __half g_WIH[24 * 768 * 8];    // [k8][o(768)][p(8)] halves, k = 8*k8+p
__device__ __half g_WHH[32 * 768 * 8];
__device__ __half g_WHD[32 * 512 * 8];    // head: key|erase|add|beta|pad
__device__ __half g_Mh[(size_t)BN * MEMN * WORDN];   // 16MB fp16 memory state

// ---------------- helpers ----------------
__device__ __forceinline__ void ffma2(float2 &d, float2 a, float2 b) {
    unsigned long long &du = reinterpret_cast<unsigned long long &>(d);
    unsigned long long au = reinterpret_cast<unsigned long long &>(a);
    unsigned long long bu = reinterpret_cast<unsigned long long &>(b);
    asm("fma.rn.f32x2 %0, %1, %2, %0;" : "+l"(du) : "l"(au), "l"(bu));
}
__device__ __forceinline__ float2 dup2(float a) { return make_float2(a, a); }
__device__ __forceinline__ float sigf(float x) { return 1.0f / (1.0f + __expf(-x)); }
__device__ __forceinline__ float softplusf(float x) {
    return fmaxf(x, 0.0f) + log1pf(__expf(-fabsf(x)));
}

// ---------------- K0: weight repack to fp16 ----------------
__global__ void ntm_prep(const float* __restrict__ W_ih, const float* __restrict__ W_hh,
                         const float* __restrict__ W_key, const float* __restrict__ W_beta,
                         const float* __restrict__ W_erase, const float* __restrict__ W_add) {
    int stride = gridDim.x * blockDim.x;
    int idx0 = blockIdx.x * blockDim.x + threadIdx.x;
    for (int i = idx0; i < 768 * 192; i += stride) {
        int o = i / 192, k = i % 192;
        g_WIH[((k >> 3) * 768 + o) * 8 + (k & 7)] = __float2half(W_ih[i]);
    }
    for (int i = idx0; i < 768 * 256; i += stride) {
        int o = i / 256, k = i % 256;
        g_WHH[((k >> 3) * 768 + o) * 8 + (k & 7)] = __float2half(W_hh[i]);
    }
    for (int i = idx0; i < 32 * 512 * 8; i += stride) {
        int k8 = i / (512 * 8);
        int r = i % (512 * 8);
        int o = r >> 3, p = r & 7;
        int k = k8 * 8 + p;
        float v = 0.0f;
        if (o < 128)       v = W_key[o * 256 + k];
        else if (o < 256)  v = W_erase[(o - 128) * 256 + k];
        else if (o < 384)  v = W_add[(o - 256) * 256 + k];
        else if (o == 384) v = W_beta[k];
        g_WHD[i] = __float2half(v);
    }
}

// ---------------- K1: persistent main kernel (1 CTA = 4 batch elems, all T steps) ----------------
__global__ __launch_bounds__(256, 1)
void ntm_main(const float* __restrict__ data, const int* __restrict__ batch_sizes,
              const int* __restrict__ unsort_idxs,
              const float* __restrict__ b_ih, const float* __restrict__ b_hh,
              const float* __restrict__ b_key, const float* __restrict__ b_beta,
              const float* __restrict__ b_erase, const float* __restrict__ b_add,
              const float* __restrict__ M0, float* __restrict__ out) {
    __shared__ __align__(16) float s_in[GINN][4];     // GRU input [k][elem]
    __shared__ __align__(16) float s_h[CTRLN][4];     // ctrl state [k][elem]
    __shared__ __align__(16) float s_key[4][WORDN];   // normalized key
    __shared__ __align__(16) float s_e[4][WORDN];     // erase (sigmoid)
    __shared__ __align__(16) float s_a[4][WORDN];     // add
    __shared__ __align__(16) float s_w[4][MEMN];      // cos -> softmax weights
    __shared__ __align__(16) float s_racc[4][2][WORDN];
    __shared__ float s_beta[4];
    __shared__ int s_len[4];
    __shared__ int s_dst[4];

    const int tid = threadIdx.x;
    const int lane = tid & 31;
    const int warp = tid >> 5;
    const int b0 = blockIdx.x * 4;
    const int j = tid;

    // ---- active lengths ----
    if (warp < 4) {
        int e = warp, cnt = 0;
        for (int t = lane; t < TN; t += 32) cnt += (batch_sizes[t] > (b0 + e)) ? 1 : 0;
        #pragma unroll
        for (int s = 16; s; s >>= 1) cnt += __shfl_xor_sync(0xffffffffu, cnt, s);
        if (lane == 0) s_len[e] = cnt;
    }
    // ---- init M (fp16) from M0 ----
    for (int i = tid; i < (MEMN * WORDN) / 2; i += 256) {
        float2 f = ((const float2*)M0)[i];
        __half2 h = __floats2half2_rn(f.x, f.y);
        #pragma unroll
        for (int e = 0; e < 4; e++)
            ((__half2*)g_Mh)[(size_t)(b0 + e) * ((MEMN * WORDN) / 2) + i] = h;
    }
    for (int i = tid; i < GINN * 4; i += 256) (&s_in[0][0])[i] = 0.0f;
    for (int i = tid; i < CTRLN * 4; i += 256) (&s_h[0][0])[i] = 0.0f;
    __syncthreads();

    const int L0 = s_len[0], L1 = s_len[1], L2 = s_len[2], L3 = s_len[3];
    const int Tmax = max(max(L0, L1), max(L2, L3));

    const float bR  = b_ih[j] + b_hh[j];
    const float bZ  = b_ih[256 + j] + b_hh[256 + j];
    const float bNi = b_ih[512 + j];
    const float bNh = b_hh[512 + j];
    const float bH1 = (j < 128) ? b_key[j] : b_erase[j - 128];
    const float bH2 = (j < 128) ? b_add[j] : ((j == 128) ? b_beta[0] : 0.0f);

    for (int t = 0; t < Tmax; ++t) {
        {
            int e = tid >> 6, d = tid & 63;
            s_in[d][e] = data[((size_t)t * BN + (b0 + e)) * DINN + d];
        }
        __syncthreads();

        // ================= GRU GEMV (fp16 weights, f32x2 accumulate) =================
        float2 ar0 = dup2(bR), ar1 = dup2(bR);
        float2 az0 = dup2(bZ), az1 = dup2(bZ);
        float2 ai0 = dup2(bNi), ai1 = dup2(bNi);
        float2 ah0 = dup2(bNh), ah1 = dup2(bNh);
        {   // gi: k over 192
            const uint4* W = (const uint4*)g_WIH;
            #pragma unroll 8
            for (int k8 = 0; k8 < 24; ++k8) {
                uint4 uwr = __ldg(&W[k8 * 768 + j]);
                uint4 uwz = __ldg(&W[k8 * 768 + 256 + j]);
                uint4 uwn = __ldg(&W[k8 * 768 + 512 + j]);
                const __half2* hr = (const __half2*)&uwr;
                const __half2* hz = (const __half2*)&uwz;
                const __half2* hn = (const __half2*)&uwn;
                #pragma unroll
                for (int q = 0; q < 4; ++q) {
                    float2 wr2 = __half22float2(hr[q]);
                    float2 wz2 = __half22float2(hz[q]);
                    float2 wn2 = __half22float2(hn[q]);
                    float4 ia = *(const float4*)&s_in[k8 * 8 + 2 * q][0];
                    float4 ib = *(const float4*)&s_in[k8 * 8 + 2 * q + 1][0];
                    float2 a01 = make_float2(ia.x, ia.y), a23 = make_float2(ia.z, ia.w);
                    float2 b01 = make_float2(ib.x, ib.y), b23 = make_float2(ib.z, ib.w);
                    ffma2(ar0, dup2(wr2.x), a01); ffma2(ar1, dup2(wr2.x), a23);
                    ffma2(az0, dup2(wz2.x), a01); ffma2(az1, dup2(wz2.x), a23);
                    ffma2(ai0, dup2(wn2.x), a01); ffma2(ai1, dup2(wn2.x), a23);
                    ffma2(ar0, dup2(wr2.y), b01); ffma2(ar1, dup2(wr2.y), b23);
                    ffma2(az0, dup2(wz2.y), b01); ffma2(az1, dup2(wz2.y), b23);
                    ffma2(ai0, dup2(wn2.y), b01); ffma2(ai1, dup2(wn2.y), b23);
                }
            }
        }
        {   // gh: k over 256
            const uint4* W = (const uint4*)g_WHH;
            #pragma unroll 8
            for (int k8 = 0; k8 < 32; ++k8) {
                uint4 uwr = __ldg(&W[k8 * 768 + j]);
                uint4 uwz = __ldg(&W[k8 * 768 + 256 + j]);
                uint4 uwn = __ldg(&W[k8 * 768 + 512 + j]);
                const __half2* hr = (const __half2*)&uwr;
                const __half2* hz = (const __half2*)&uwz;
                const __half2* hn = (const __half2*)&uwn;
                #pragma unroll
                for (int q = 0; q < 4; ++q) {
                    float2 wr2 = __half22float2(hr[q]);
                    float2 wz2 = __half22float2(hz[q]);
                    float2 wn2 = __half22float2(hn[q]);
                    float4 ia = *(const float4*)&s_h[k8 * 8 + 2 * q][0];
                    float4 ib = *(const float4*)&s_h[k8 * 8 + 2 * q + 1][0];
                    float2 a01 = make_float2(ia.x, ia.y), a23 = make_float2(ia.z, ia.w);
                    float2 b01 = make_float2(ib.x, ib.y), b23 = make_float2(ib.z, ib.w);
                    ffma2(ar0, dup2(wr2.x), a01); ffma2(ar1, dup2(wr2.x), a23);
                    ffma2(az0, dup2(wz2.x), a01); ffma2(az1, dup2(wz2.x), a23);
                    ffma2(ah0, dup2(wn2.x), a01); ffma2(ah1, dup2(wn2.x), a23);
                    ffma2(ar0, dup2(wr2.y), b01); ffma2(ar1, dup2(wr2.y), b23);
                    ffma2(az0, dup2(wz2.y), b01); ffma2(az1, dup2(wz2.y), b23);
                    ffma2(ah0, dup2(wn2.y), b01); ffma2(ah1, dup2(wn2.y), b23);
                }
            }
        }
        // ---- gates ----
        float hn_[4];
        {
            float4 hold = *(const float4*)&s_h[j][0];
            float pr[4] = {ar0.x, ar0.y, ar1.x, ar1.y};
            float pz[4] = {az0.x, az0.y, az1.x, az1.y};
            float pi[4] = {ai0.x, ai0.y, ai1.x, ai1.y};
            float ph[4] = {ah0.x, ah0.y, ah1.x, ah1.y};
            float ho[4] = {hold.x, hold.y, hold.z, hold.w};
            #pragma unroll
            for (int e = 0; e < 4; e++) {
                float r = sigf(pr[e]);
                float z = sigf(pz[e]);
                float n = tanhf(pi[e] + r * ph[e]);
                hn_[e] = (1.0f - z) * n + z * ho[e];
            }
        }
        __syncthreads();
        if (t < L0) s_h[j][0] = hn_[0];
        if (t < L1) s_h[j][1] = hn_[1];
        if (t < L2) s_h[j][2] = hn_[2];
        if (t < L3) s_h[j][3] = hn_[3];
        __syncthreads();

        // ================= head GEMV =================
        float2 h10 = dup2(bH1), h11 = dup2(bH1);
        float2 h20 = dup2(bH2), h21 = dup2(bH2);
        {
            const uint4* W = (const uint4*)g_WHD;
            #pragma unroll 8
            for (int k8 = 0; k8 < 32; ++k8) {
                uint4 uw1 = __ldg(&W[k8 * 512 + j]);
                uint4 uw2 = __ldg(&W[k8 * 512 + 256 + j]);
                const __half2* h1p = (const __half2*)&uw1;
                const __half2* h2p = (const __half2*)&uw2;
                #pragma unroll
                for (int q = 0; q < 4; ++q) {
                    float2 w12 = __half22float2(h1p[q]);
                    float2 w22 = __half22float2(h2p[q]);
                    float4 ia = *(const float4*)&s_h[k8 * 8 + 2 * q][0];
                    float4 ib = *(const float4*)&s_h[k8 * 8 + 2 * q + 1][0];
                    float2 a01 = make_float2(ia.x, ia.y), a23 = make_float2(ia.z, ia.w);
                    float2 b01 = make_float2(ib.x, ib.y), b23 = make_float2(ib.z, ib.w);
                    ffma2(h10, dup2(w12.x), a01); ffma2(h11, dup2(w12.x), a23);
                    ffma2(h20, dup2(w22.x), a01); ffma2(h21, dup2(w22.x), a23);
                    ffma2(h10, dup2(w12.y), b01); ffma2(h11, dup2(w12.y), b23);
                    ffma2(h20, dup2(w22.y), b01); ffma2(h21, dup2(w22.y), b23);
                }
            }
        }
        {
            float v1[4] = {h10.x, h10.y, h11.x, h11.y};
            float v2[4] = {h20.x, h20.y, h21.x, h21.y};
            #pragma unroll
            for (int e = 0; e < 4; e++) {
                if (j < 128) {
                    s_key[e][j] = tanhf(v1[e]);
                    s_a[e][j] = v2[e];
                } else {
                    s_e[e][j - 128] = sigf(v1[e]);
                    if (j == 128) s_beta[e] = softplusf(v2[e]);
                }
            }
        }
        __syncthreads();

        // ---- normalize key ----
        if (warp < 4) {
            int e = warp;
            float4 kv = *(const float4*)&s_key[e][lane * 4];
            float ss = kv.x * kv.x + kv.y * kv.y + kv.z * kv.z + kv.w * kv.w;
            #pragma unroll
            for (int s = 16; s; s >>= 1) ss += __shfl_xor_sync(0xffffffffu, ss, s);
            float inv = 1.0f / (sqrtf(ss) + EPSF);
            kv.x *= inv; kv.y *= inv; kv.z *= inv; kv.w *= inv;
            *(float4*)&s_key[e][lane * 4] = kv;
        }
        __syncthreads();

        // ================= pass 1: cos over fp16 M, 2 warps/elem =================
        {
            int e = warp >> 1, half = warp & 1;
            if (t < s_len[e]) {
                const __half* Me = g_Mh + (size_t)(b0 + e) * (MEMN * WORDN);
                int rl = lane >> 3;
                int cc = (lane & 7) * 16;   // half index
                float kf[16];
                #pragma unroll
                for (int i = 0; i < 16; i++) kf[i] = s_key[e][cc + i];
                #pragma unroll 4
                for (int mb = half * 64; mb < half * 64 + 64; mb += 4) {
                    int m = mb + rl;
                    const uint4* Mr = (const uint4*)(Me + m * WORDN + cc);
                    uint4 u0 = __ldg(&Mr[0]);
                    uint4 u1 = __ldg(&Mr[1]);
                    const __half2* p0 = (const __half2*)&u0;
                    const __half2* p1 = (const __half2*)&u1;
                    float dot = 0.f, nrm = 0.f;
                    #pragma unroll
                    for (int q = 0; q < 4; q++) {
                        float2 f0 = __half22float2(p0[q]);
                        float2 f1 = __half22float2(p1[q]);
                        dot = fmaf(f0.x, kf[2 * q], dot);
                        dot = fmaf(f0.y, kf[2 * q + 1], dot);
                        dot = fmaf(f1.x, kf[8 + 2 * q], dot);
                        dot = fmaf(f1.y, kf[8 + 2 * q + 1], dot);
                        nrm = fmaf(f0.x, f0.x, nrm);
                        nrm = fmaf(f0.y, f0.y, nrm);
                        nrm = fmaf(f1.x, f1.x, nrm);
                        nrm = fmaf(f1.y, f1.y, nrm);
                    }
                    #pragma unroll
                    for (int s = 1; s < 8; s <<= 1) {
                        dot += __shfl_xor_sync(0xffffffffu, dot, s);
                        nrm += __shfl_xor_sync(0xffffffffu, nrm, s);
                    }
                    if ((lane & 7) == 0) s_w[e][m] = dot / (sqrtf(nrm) + EPSF);
                }
            }
        }
        __syncthreads();

        // ---- softmax ----
        if (warp < 4 && t < s_len[warp]) {
            int e = warp;
            float beta = s_beta[e];
            float v0 = beta * s_w[e][lane];
            float v1 = beta * s_w[e][lane + 32];
            float v2 = beta * s_w[e][lane + 64];
            float v3 = beta * s_w[e][lane + 96];
            float mx = fmaxf(fmaxf(v0, v1), fmaxf(v2, v3));
            #pragma unroll
            for (int s = 16; s; s >>= 1) mx = fmaxf(mx, __shfl_xor_sync(0xffffffffu, mx, s));
            v0 = __expf(v0 - mx); v1 = __expf(v1 - mx);
            v2 = __expf(v2 - mx); v3 = __expf(v3 - mx);
            float sum = v0 + v1 + v2 + v3;
            #pragma unroll
            for (int s = 16; s; s >>= 1) sum += __shfl_xor_sync(0xffffffffu, sum, s);
            float inv = 1.0f / sum;
            s_w[e][lane] = v0 * inv;
            s_w[e][lane + 32] = v1 * inv;
            s_w[e][lane + 64] = v2 * inv;
            s_w[e][lane + 96] = v3 * inv;
        }
        __syncthreads();

        // ================= pass 2: read + M update (fp16), 2 warps/elem =================
        {
            int e = warp >> 1, half = warp & 1;
            if (t < s_len[e]) {
                __half* Me = g_Mh + (size_t)(b0 + e) * (MEMN * WORDN);
                float4 e4 = *(const float4*)&s_e[e][lane * 4];
                float4 a4 = *(const float4*)&s_a[e][lane * 4];
                float4 racc = make_float4(0.f, 0.f, 0.f, 0.f);
                #pragma unroll 8
                for (int m = half * 64; m < half * 64 + 64; ++m) {
                    float wm = s_w[e][m];
                    uint2* Mr = (uint2*)(Me + m * WORDN + lane * 4);
                    uint2 u = *Mr;
                    __half2* hp = (__half2*)&u;
                    float2 m01 = __half22float2(hp[0]);
                    float2 m23 = __half22float2(hp[1]);
                    racc.x = fmaf(wm, m01.x, racc.x);
                    racc.y = fmaf(wm, m01.y, racc.y);
                    racc.z = fmaf(wm, m23.x, racc.z);
                    racc.w = fmaf(wm, m23.y, racc.w);
                    float f0 = fmaf(-wm, e4.x, 1.0f);
                    float f1 = fmaf(-wm, e4.y, 1.0f);
                    float f2 = fmaf(-wm, e4.z, 1.0f);
                    float f3 = fmaf(-wm, e4.w, 1.0f);
                    float n0 = fmaf(m01.x, f0, wm * a4.x);
                    float n1 = fmaf(m01.y, f1, wm * a4.y);
                    float n2 = fmaf(m23.x, f2, wm * a4.z);
                    float n3 = fmaf(m23.y, f3, wm * a4.w);
                    hp[0] = __floats2half2_rn(n0, n1);
                    hp[1] = __floats2half2_rn(n2, n3);
                    *Mr = u;
                }
                *(float4*)&s_racc[e][half][lane * 4] = racc;
            }
        }
        __syncthreads();
        for (int idx = tid; idx < 512; idx += 256) {
            int e = idx >> 7, w = idx & 127;
            if (t < s_len[e]) s_in[64 + w][e] = s_racc[e][0][w] + s_racc[e][1][w];
        }
        __syncthreads();
    }

    // ---- epilogue ----
    for (int q = tid; q < BN; q += 256) {
        int u = unsort_idxs[q];
        if (u >= b0 && u < b0 + 4) s_dst[u - b0] = q;
    }
    __syncthreads();
    #pragma unroll
    for (int e = 0; e < 4; e++) {
        out[(size_t)s_dst[e] * CTRLN + tid] = s_h[tid][e];
    }
    for (int idx = tid; idx < 512; idx += 256) {
        int e = idx >> 7, w = idx & 127;
        out[(size_t)BN * CTRLN + (size_t)s_dst[e] * WORDN + w] = s_in[64 + w][e];
    }
}

// ---------------- launch ----------------
extern "C" void kernel_launch(void* const* d_in, const int* in_sizes, int n_in,
                              void* d_out, int out_size) {
    const float* data        = (const float*)d_in[0];
    const int*   batch_sizes = (const int*)d_in[1];
    const int*   unsort      = (const int*)d_in[2];
    const float* W_ih        = (const float*)d_in[3];
    const float* b_ih        = (const float*)d_in[4];
    const float* W_hh        = (const float*)d_in[5];
    const float* b_hh        = (const float*)d_in[6];
    const float* W_key       = (const float*)d_in[7];
    const float* b_key       = (const float*)d_in[8];
    const float* W_beta      = (const float*)d_in[9];
    const float* b_beta      = (const float*)d_in[10];
    const float* W_erase     = (const float*)d_in[11];
    const float* b_erase     = (const float*)d_in[12];
    const float* W_add       = (const float*)d_in[13];
    const float* b_add       = (const float*)d_in[14];
    const float* M0          = (const float*)d_in[15];

    ntm_prep<<<256, 256>>>(W_ih, W_hh, W_key, W_beta, W_erase, W_add);
    ntm_main<<<128, 256>>>(data, batch_sizes, unsort,
                           b_ih, b_hh, b_key, b_beta, b_erase, b_add,
                           M0, (float*)d_out);
}

// round 3
// speedup vs baseline: 1.3428x; 1.0244x over previous
#include <cuda_runtime.h>
#include <cuda_fp16.h>
#include <math.h>

// Problem constants
#define CTRLN 256
#define WORDN 128
#define MEMN  128
#define DINN  64
#define BN    512
#define TN    512
#define GINN  192            // D_IN + WORD
#define EPSF  1e-6f

// ---------------- device scratch (static, no allocs) ----------------
__device__ __half g_WIH[24 * 768 * 8];    // [k8][o(768)][p(8)] halves, k = 8*k8+p
__device__ __half g_WHH[32 * 768 * 8];
__device__ __half g_WHD[32 * 512 * 8];    // head: key|erase|add|beta|pad
__device__ __half g_Mh[(size_t)BN * MEMN * WORDN];   // 16MB fp16 memory state

// ---------------- helpers ----------------
__device__ __forceinline__ void ffma2(float2 &d, float2 a, float2 b) {
    unsigned long long &du = reinterpret_cast<unsigned long long &>(d);
    unsigned long long au = reinterpret_cast<unsigned long long &>(a);
    unsigned long long bu = reinterpret_cast<unsigned long long &>(b);
    asm("fma.rn.f32x2 %0, %1, %2, %0;" : "+l"(du) : "l"(au), "l"(bu));
}
__device__ __forceinline__ float2 dup2(float a) { return make_float2(a, a); }
__device__ __forceinline__ float sigf(float x) { return 1.0f / (1.0f + __expf(-x)); }
__device__ __forceinline__ float softplusf(float x) {
    return fmaxf(x, 0.0f) + log1pf(__expf(-fabsf(x)));
}

// ---------------- K0: weight repack to fp16 ----------------
__global__ void ntm_prep(const float* __restrict__ W_ih, const float* __restrict__ W_hh,
                         const float* __restrict__ W_key, const float* __restrict__ W_beta,
                         const float* __restrict__ W_erase, const float* __restrict__ W_add) {
    int stride = gridDim.x * blockDim.x;
    int idx0 = blockIdx.x * blockDim.x + threadIdx.x;
    for (int i = idx0; i < 768 * 192; i += stride) {
        int o = i / 192, k = i % 192;
        g_WIH[((k >> 3) * 768 + o) * 8 + (k & 7)] = __float2half(W_ih[i]);
    }
    for (int i = idx0; i < 768 * 256; i += stride) {
        int o = i / 256, k = i % 256;
        g_WHH[((k >> 3) * 768 + o) * 8 + (k & 7)] = __float2half(W_hh[i]);
    }
    for (int i = idx0; i < 32 * 512 * 8; i += stride) {
        int k8 = i / (512 * 8);
        int r = i % (512 * 8);
        int o = r >> 3, p = r & 7;
        int k = k8 * 8 + p;
        float v = 0.0f;
        if (o < 128)       v = W_key[o * 256 + k];
        else if (o < 256)  v = W_erase[(o - 128) * 256 + k];
        else if (o < 384)  v = W_add[(o - 256) * 256 + k];
        else if (o == 384) v = W_beta[k];
        g_WHD[i] = __float2half(v);
    }
}

// ---------------- K1: persistent main kernel (1 CTA = 4 batch elems, 512 threads) ----------------
__global__ __launch_bounds__(512, 1)
void ntm_main(const float* __restrict__ data, const int* __restrict__ batch_sizes,
              const int* __restrict__ unsort_idxs,
              const float* __restrict__ b_ih, const float* __restrict__ b_hh,
              const float* __restrict__ b_key, const float* __restrict__ b_beta,
              const float* __restrict__ b_erase, const float* __restrict__ b_add,
              const float* __restrict__ M0, float* __restrict__ out) {
    __shared__ __align__(16) float s_in[GINN][4];     // GRU input [k][elem]
    __shared__ __align__(16) float s_h[CTRLN][4];     // ctrl state [k][elem]
    __shared__ __align__(16) float s_red[16][256];    // split-k partial reduction
    __shared__ __align__(16) float s_key[4][WORDN];
    __shared__ __align__(16) float s_e[4][WORDN];
    __shared__ __align__(16) float s_a[4][WORDN];
    __shared__ __align__(16) float s_w[4][MEMN];
    __shared__ __align__(16) float s_racc[4][4][WORDN];
    __shared__ float s_beta[4];
    __shared__ int s_len[4];
    __shared__ int s_dst[4];

    const int tid = threadIdx.x;
    const int lane = tid & 31;
    const int warp = tid >> 5;
    const int b0 = blockIdx.x * 4;
    const int j = tid & 255;     // GRU output index
    const int sk = tid >> 8;     // k-half for split-K

    // ---- active lengths ----
    if (warp < 4) {
        int e = warp, cnt = 0;
        for (int t = lane; t < TN; t += 32) cnt += (batch_sizes[t] > (b0 + e)) ? 1 : 0;
        #pragma unroll
        for (int s = 16; s; s >>= 1) cnt += __shfl_xor_sync(0xffffffffu, cnt, s);
        if (lane == 0) s_len[e] = cnt;
    }
    // ---- init M (fp16) from M0 ----
    for (int i = tid; i < (MEMN * WORDN) / 2; i += 512) {
        float2 f = ((const float2*)M0)[i];
        __half2 h = __floats2half2_rn(f.x, f.y);
        #pragma unroll
        for (int e = 0; e < 4; e++)
            ((__half2*)g_Mh)[(size_t)(b0 + e) * ((MEMN * WORDN) / 2) + i] = h;
    }
    for (int i = tid; i < GINN * 4; i += 512) (&s_in[0][0])[i] = 0.0f;
    for (int i = tid; i < CTRLN * 4; i += 512) (&s_h[0][0])[i] = 0.0f;
    __syncthreads();

    const int L0 = s_len[0], L1 = s_len[1], L2 = s_len[2], L3 = s_len[3];
    const int Tmax = max(max(L0, L1), max(L2, L3));

    // ---- biases: GRU (only sk==0 threads seed them), head (per-thread output) ----
    const float bR  = (sk == 0) ? (b_ih[j] + b_hh[j]) : 0.0f;
    const float bZ  = (sk == 0) ? (b_ih[256 + j] + b_hh[256 + j]) : 0.0f;
    const float bNi = (sk == 0) ? b_ih[512 + j] : 0.0f;
    const float bNh = (sk == 0) ? b_hh[512 + j] : 0.0f;
    const int o = tid;           // head output index 0..511
    const float bHD = (o < 128) ? b_key[o]
                    : (o < 256) ? b_erase[o - 128]
                    : (o < 384) ? b_add[o - 256]
                    : ((o == 384) ? b_beta[0] : 0.0f);

    for (int t = 0; t < Tmax; ++t) {
        if (tid < 256) {
            int e = tid >> 6, d = tid & 63;
            s_in[d][e] = data[((size_t)t * BN + (b0 + e)) * DINN + d];
        }
        __syncthreads();

        // ================= GRU GEMV: split-K over 2 thread groups =================
        float2 ar0 = dup2(bR), ar1 = dup2(bR);
        float2 az0 = dup2(bZ), az1 = dup2(bZ);
        float2 ai0 = dup2(bNi), ai1 = dup2(bNi);
        float2 ah0 = dup2(bNh), ah1 = dup2(bNh);
        {   // gi: k over 192 -> 24 k8-iters, half each
            const uint4* W = (const uint4*)g_WIH;
            #pragma unroll 4
            for (int k8 = sk * 12; k8 < sk * 12 + 12; ++k8) {
                uint4 uwr = __ldg(&W[k8 * 768 + j]);
                uint4 uwz = __ldg(&W[k8 * 768 + 256 + j]);
                uint4 uwn = __ldg(&W[k8 * 768 + 512 + j]);
                const __half2* hr = (const __half2*)&uwr;
                const __half2* hz = (const __half2*)&uwz;
                const __half2* hn = (const __half2*)&uwn;
                #pragma unroll
                for (int q = 0; q < 4; ++q) {
                    float2 wr2 = __half22float2(hr[q]);
                    float2 wz2 = __half22float2(hz[q]);
                    float2 wn2 = __half22float2(hn[q]);
                    float4 ia = *(const float4*)&s_in[k8 * 8 + 2 * q][0];
                    float4 ib = *(const float4*)&s_in[k8 * 8 + 2 * q + 1][0];
                    float2 a01 = make_float2(ia.x, ia.y), a23 = make_float2(ia.z, ia.w);
                    float2 b01 = make_float2(ib.x, ib.y), b23 = make_float2(ib.z, ib.w);
                    ffma2(ar0, dup2(wr2.x), a01); ffma2(ar1, dup2(wr2.x), a23);
                    ffma2(az0, dup2(wz2.x), a01); ffma2(az1, dup2(wz2.x), a23);
                    ffma2(ai0, dup2(wn2.x), a01); ffma2(ai1, dup2(wn2.x), a23);
                    ffma2(ar0, dup2(wr2.y), b01); ffma2(ar1, dup2(wr2.y), b23);
                    ffma2(az0, dup2(wz2.y), b01); ffma2(az1, dup2(wz2.y), b23);
                    ffma2(ai0, dup2(wn2.y), b01); ffma2(ai1, dup2(wn2.y), b23);
                }
            }
        }
        {   // gh: k over 256 -> 32 k8-iters, half each
            const uint4* W = (const uint4*)g_WHH;
            #pragma unroll 4
            for (int k8 = sk * 16; k8 < sk * 16 + 16; ++k8) {
                uint4 uwr = __ldg(&W[k8 * 768 + j]);
                uint4 uwz = __ldg(&W[k8 * 768 + 256 + j]);
                uint4 uwn = __ldg(&W[k8 * 768 + 512 + j]);
                const __half2* hr = (const __half2*)&uwr;
                const __half2* hz = (const __half2*)&uwz;
                const __half2* hn = (const __half2*)&uwn;
                #pragma unroll
                for (int q = 0; q < 4; ++q) {
                    float2 wr2 = __half22float2(hr[q]);
                    float2 wz2 = __half22float2(hz[q]);
                    float2 wn2 = __half22float2(hn[q]);
                    float4 ia = *(const float4*)&s_h[k8 * 8 + 2 * q][0];
                    float4 ib = *(const float4*)&s_h[k8 * 8 + 2 * q + 1][0];
                    float2 a01 = make_float2(ia.x, ia.y), a23 = make_float2(ia.z, ia.w);
                    float2 b01 = make_float2(ib.x, ib.y), b23 = make_float2(ib.z, ib.w);
                    ffma2(ar0, dup2(wr2.x), a01); ffma2(ar1, dup2(wr2.x), a23);
                    ffma2(az0, dup2(wz2.x), a01); ffma2(az1, dup2(wz2.x), a23);
                    ffma2(ah0, dup2(wn2.x), a01); ffma2(ah1, dup2(wn2.x), a23);
                    ffma2(ar0, dup2(wr2.y), b01); ffma2(ar1, dup2(wr2.y), b23);
                    ffma2(az0, dup2(wz2.y), b01); ffma2(az1, dup2(wz2.y), b23);
                    ffma2(ah0, dup2(wn2.y), b01); ffma2(ah1, dup2(wn2.y), b23);
                }
            }
        }
        // ---- reduce the two k-halves through SMEM ----
        {
            float acc[16] = {ar0.x, ar0.y, ar1.x, ar1.y,
                             az0.x, az0.y, az1.x, az1.y,
                             ai0.x, ai0.y, ai1.x, ai1.y,
                             ah0.x, ah0.y, ah1.x, ah1.y};
            if (sk == 1) {
                #pragma unroll
                for (int c = 0; c < 16; c++) s_red[c][j] = acc[c];
            }
            __syncthreads();
            if (sk == 0) {
                #pragma unroll
                for (int c = 0; c < 16; c++) acc[c] += s_red[c][j];
                float4 hold = *(const float4*)&s_h[j][0];
                float ho[4] = {hold.x, hold.y, hold.z, hold.w};
                float hn_[4];
                #pragma unroll
                for (int e = 0; e < 4; e++) {
                    float r = sigf(acc[e]);
                    float z = sigf(acc[4 + e]);
                    float n = tanhf(acc[8 + e] + r * acc[12 + e]);
                    hn_[e] = (1.0f - z) * n + z * ho[e];
                }
                if (t < L0) s_h[j][0] = hn_[0];
                if (t < L1) s_h[j][1] = hn_[1];
                if (t < L2) s_h[j][2] = hn_[2];
                if (t < L3) s_h[j][3] = hn_[3];
            }
        }
        __syncthreads();

        // ================= head GEMV: 512 outputs, 1 per thread, full K =================
        float2 hd0 = dup2(bHD), hd1 = dup2(bHD);
        {
            const uint4* W = (const uint4*)g_WHD;
            #pragma unroll 8
            for (int k8 = 0; k8 < 32; ++k8) {
                uint4 uw = __ldg(&W[k8 * 512 + o]);
                const __half2* hp = (const __half2*)&uw;
                #pragma unroll
                for (int q = 0; q < 4; ++q) {
                    float2 w2 = __half22float2(hp[q]);
                    float4 ia = *(const float4*)&s_h[k8 * 8 + 2 * q][0];
                    float4 ib = *(const float4*)&s_h[k8 * 8 + 2 * q + 1][0];
                    float2 a01 = make_float2(ia.x, ia.y), a23 = make_float2(ia.z, ia.w);
                    float2 b01 = make_float2(ib.x, ib.y), b23 = make_float2(ib.z, ib.w);
                    ffma2(hd0, dup2(w2.x), a01); ffma2(hd1, dup2(w2.x), a23);
                    ffma2(hd0, dup2(w2.y), b01); ffma2(hd1, dup2(w2.y), b23);
                }
            }
        }
        {
            float v[4] = {hd0.x, hd0.y, hd1.x, hd1.y};
            #pragma unroll
            for (int e = 0; e < 4; e++) {
                if (o < 128)       s_key[e][o] = tanhf(v[e]);
                else if (o < 256)  s_e[e][o - 128] = sigf(v[e]);
                else if (o < 384)  s_a[e][o - 256] = v[e];
                else if (o == 384) s_beta[e] = softplusf(v[e]);
            }
        }
        __syncthreads();

        // ---- normalize key (warps 0-3) ----
        if (warp < 4) {
            int e = warp;
            float4 kv = *(const float4*)&s_key[e][lane * 4];
            float ss = kv.x * kv.x + kv.y * kv.y + kv.z * kv.z + kv.w * kv.w;
            #pragma unroll
            for (int s = 16; s; s >>= 1) ss += __shfl_xor_sync(0xffffffffu, ss, s);
            float inv = 1.0f / (sqrtf(ss) + EPSF);
            kv.x *= inv; kv.y *= inv; kv.z *= inv; kv.w *= inv;
            *(float4*)&s_key[e][lane * 4] = kv;
        }
        __syncthreads();

        // ================= pass 1: cos over fp16 M, 4 warps/elem =================
        {
            int e = warp >> 2, qt = warp & 3;
            if (t < s_len[e]) {
                const __half* Me = g_Mh + (size_t)(b0 + e) * (MEMN * WORDN);
                int rl = lane >> 3;
                int cc = (lane & 7) * 16;
                float kf[16];
                #pragma unroll
                for (int i = 0; i < 16; i++) kf[i] = s_key[e][cc + i];
                #pragma unroll 4
                for (int mb = qt * 32; mb < qt * 32 + 32; mb += 4) {
                    int m = mb + rl;
                    const uint4* Mr = (const uint4*)(Me + m * WORDN + cc);
                    uint4 u0 = __ldg(&Mr[0]);
                    uint4 u1 = __ldg(&Mr[1]);
                    const __half2* p0 = (const __half2*)&u0;
                    const __half2* p1 = (const __half2*)&u1;
                    float dot = 0.f, nrm = 0.f;
                    #pragma unroll
                    for (int q = 0; q < 4; q++) {
                        float2 f0 = __half22float2(p0[q]);
                        float2 f1 = __half22float2(p1[q]);
                        dot = fmaf(f0.x, kf[2 * q], dot);
                        dot = fmaf(f0.y, kf[2 * q + 1], dot);
                        dot = fmaf(f1.x, kf[8 + 2 * q], dot);
                        dot = fmaf(f1.y, kf[8 + 2 * q + 1], dot);
                        nrm = fmaf(f0.x, f0.x, nrm);
                        nrm = fmaf(f0.y, f0.y, nrm);
                        nrm = fmaf(f1.x, f1.x, nrm);
                        nrm = fmaf(f1.y, f1.y, nrm);
                    }
                    #pragma unroll
                    for (int s = 1; s < 8; s <<= 1) {
                        dot += __shfl_xor_sync(0xffffffffu, dot, s);
                        nrm += __shfl_xor_sync(0xffffffffu, nrm, s);
                    }
                    if ((lane & 7) == 0) s_w[e][m] = dot / (sqrtf(nrm) + EPSF);
                }
            }
        }
        __syncthreads();

        // ---- softmax (warps 0-3) ----
        if (warp < 4 && t < s_len[warp]) {
            int e = warp;
            float beta = s_beta[e];
            float v0 = beta * s_w[e][lane];
            float v1 = beta * s_w[e][lane + 32];
            float v2 = beta * s_w[e][lane + 64];
            float v3 = beta * s_w[e][lane + 96];
            float mx = fmaxf(fmaxf(v0, v1), fmaxf(v2, v3));
            #pragma unroll
            for (int s = 16; s; s >>= 1) mx = fmaxf(mx, __shfl_xor_sync(0xffffffffu, mx, s));
            v0 = __expf(v0 - mx); v1 = __expf(v1 - mx);
            v2 = __expf(v2 - mx); v3 = __expf(v3 - mx);
            float sum = v0 + v1 + v2 + v3;
            #pragma unroll
            for (int s = 16; s; s >>= 1) sum += __shfl_xor_sync(0xffffffffu, sum, s);
            float inv = 1.0f / sum;
            s_w[e][lane] = v0 * inv;
            s_w[e][lane + 32] = v1 * inv;
            s_w[e][lane + 64] = v2 * inv;
            s_w[e][lane + 96] = v3 * inv;
        }
        __syncthreads();

        // ================= pass 2: read + M update (fp16), 4 warps/elem =================
        {
            int e = warp >> 2, qt = warp & 3;
            if (t < s_len[e]) {
                __half* Me = g_Mh + (size_t)(b0 + e) * (MEMN * WORDN);
                float4 e4 = *(const float4*)&s_e[e][lane * 4];
                float4 a4 = *(const float4*)&s_a[e][lane * 4];
                float4 racc = make_float4(0.f, 0.f, 0.f, 0.f);
                #pragma unroll 8
                for (int m = qt * 32; m < qt * 32 + 32; ++m) {
                    float wm = s_w[e][m];
                    uint2* Mr = (uint2*)(Me + m * WORDN + lane * 4);
                    uint2 u = *Mr;
                    __half2* hp = (__half2*)&u;
                    float2 m01 = __half22float2(hp[0]);
                    float2 m23 = __half22float2(hp[1]);
                    racc.x = fmaf(wm, m01.x, racc.x);
                    racc.y = fmaf(wm, m01.y, racc.y);
                    racc.z = fmaf(wm, m23.x, racc.z);
                    racc.w = fmaf(wm, m23.y, racc.w);
                    float f0 = fmaf(-wm, e4.x, 1.0f);
                    float f1 = fmaf(-wm, e4.y, 1.0f);
                    float f2 = fmaf(-wm, e4.z, 1.0f);
                    float f3 = fmaf(-wm, e4.w, 1.0f);
                    float n0 = fmaf(m01.x, f0, wm * a4.x);
                    float n1 = fmaf(m01.y, f1, wm * a4.y);
                    float n2 = fmaf(m23.x, f2, wm * a4.z);
                    float n3 = fmaf(m23.y, f3, wm * a4.w);
                    hp[0] = __floats2half2_rn(n0, n1);
                    hp[1] = __floats2half2_rn(n2, n3);
                    *Mr = u;
                }
                *(float4*)&s_racc[e][qt][lane * 4] = racc;
            }
        }
        __syncthreads();
        {
            int e = tid >> 7, w = tid & 127;
            if (t < s_len[e])
                s_in[64 + w][e] = (s_racc[e][0][w] + s_racc[e][1][w])
                                + (s_racc[e][2][w] + s_racc[e][3][w]);
        }
        __syncthreads();
    }

    // ---- epilogue ----
    for (int q = tid; q < BN; q += 512) {
        int u = unsort_idxs[q];
        if (u >= b0 && u < b0 + 4) s_dst[u - b0] = q;
    }
    __syncthreads();
    if (tid < 256) {
        #pragma unroll
        for (int e = 0; e < 4; e++)
            out[(size_t)s_dst[e] * CTRLN + tid] = s_h[tid][e];
    }
    {
        int e = tid >> 7, w = tid & 127;
        out[(size_t)BN * CTRLN + (size_t)s_dst[e] * WORDN + w] = s_in[64 + w][e];
    }
}

// ---------------- launch ----------------
extern "C" void kernel_launch(void* const* d_in, const int* in_sizes, int n_in,
                              void* d_out, int out_size) {
    const float* data        = (const float*)d_in[0];
    const int*   batch_sizes = (const int*)d_in[1];
    const int*   unsort      = (const int*)d_in[2];
    const float* W_ih        = (const float*)d_in[3];
    const float* b_ih        = (const float*)d_in[4];
    const float* W_hh        = (const float*)d_in[5];
    const float* b_hh        = (const float*)d_in[6];
    const float* W_key       = (const float*)d_in[7];
    const float* b_key       = (const float*)d_in[8];
    const float* W_beta      = (const float*)d_in[9];
    const float* b_beta      = (const float*)d_in[10];
    const float* W_erase     = (const float*)d_in[11];
    const float* b_erase     = (const float*)d_in[12];
    const float* W_add       = (const float*)d_in[13];
    const float* b_add       = (const float*)d_in[14];
    const float* M0          = (const float*)d_in[15];

    ntm_prep<<<256, 256>>>(W_ih, W_hh, W_key, W_beta, W_erase, W_add);
    ntm_main<<<128, 512>>>(data, batch_sizes, unsort,
                           b_ih, b_hh, b_key, b_beta, b_erase, b_add,
                           M0, (float*)d_out);
}

// round 4
// speedup vs baseline: 1.4479x; 1.0782x over previous
#include <cuda_runtime.h>
#include <cuda_fp16.h>
#include <math.h>

// Problem constants
#define CTRLN 256
#define WORDN 128
#define MEMN  128
#define DINN  64
#define BN    512
#define TN    512
#define GINN  192            // D_IN + WORD
#define EPSF  1e-6f

// ---------------- device scratch (static, no allocs) ----------------
__device__ __half g_WIH[24 * 768 * 8];    // [k8][o(768)][p(8)] halves, k = 8*k8+p
__device__ __half g_WHH[32 * 768 * 8];
__device__ __half g_WHD[32 * 512 * 8];    // head: key|erase|add|beta|pad
__device__ __half g_Mh[(size_t)BN * MEMN * WORDN];   // 16MB fp16 memory state

// ---------------- helpers ----------------
__device__ __forceinline__ void ffma2(float2 &d, float2 a, float2 b) {
    unsigned long long &du = reinterpret_cast<unsigned long long &>(d);
    unsigned long long au = reinterpret_cast<unsigned long long &>(a);
    unsigned long long bu = reinterpret_cast<unsigned long long &>(b);
    asm("fma.rn.f32x2 %0, %1, %2, %0;" : "+l"(du) : "l"(au), "l"(bu));
}
__device__ __forceinline__ float2 dup2(float a) { return make_float2(a, a); }
__device__ __forceinline__ float sigf(float x) { return 1.0f / (1.0f + __expf(-x)); }
__device__ __forceinline__ float softplusf(float x) {
    return fmaxf(x, 0.0f) + log1pf(__expf(-fabsf(x)));
}
#define BARN(id, cnt) asm volatile("bar.sync %0, %1;" :: "r"(id), "r"(cnt) : "memory")

// ---------------- K0: weight repack to fp16 ----------------
__global__ void ntm_prep(const float* __restrict__ W_ih, const float* __restrict__ W_hh,
                         const float* __restrict__ W_key, const float* __restrict__ W_beta,
                         const float* __restrict__ W_erase, const float* __restrict__ W_add) {
    int stride = gridDim.x * blockDim.x;
    int idx0 = blockIdx.x * blockDim.x + threadIdx.x;
    for (int i = idx0; i < 768 * 192; i += stride) {
        int o = i / 192, k = i % 192;
        g_WIH[((k >> 3) * 768 + o) * 8 + (k & 7)] = __float2half(W_ih[i]);
    }
    for (int i = idx0; i < 768 * 256; i += stride) {
        int o = i / 256, k = i % 256;
        g_WHH[((k >> 3) * 768 + o) * 8 + (k & 7)] = __float2half(W_hh[i]);
    }
    for (int i = idx0; i < 32 * 512 * 8; i += stride) {
        int k8 = i / (512 * 8);
        int r = i % (512 * 8);
        int o = r >> 3, p = r & 7;
        int k = k8 * 8 + p;
        float v = 0.0f;
        if (o < 128)       v = W_key[o * 256 + k];
        else if (o < 256)  v = W_erase[(o - 128) * 256 + k];
        else if (o < 384)  v = W_add[(o - 256) * 256 + k];
        else if (o == 384) v = W_beta[k];
        g_WHD[i] = __float2half(v);
    }
}

// ---------------- GEMV_P: gh (K=256) + gi_x (K=64) for output j, 4 elems ----------------
__device__ __forceinline__ void gemv_P(int j, float bR, float bZ, float bNi, float bNh,
                                       const float (*s_in)[4], const float (*s_h)[4],
                                       float (*s_redB)[256]) {
    float2 ar0 = dup2(bR), ar1 = dup2(bR);
    float2 az0 = dup2(bZ), az1 = dup2(bZ);
    float2 ai0 = dup2(bNi), ai1 = dup2(bNi);
    float2 ah0 = dup2(bNh), ah1 = dup2(bNh);
    {   // gi_x: k8 0..7 over x rows of s_in
        const uint4* W = (const uint4*)g_WIH;
        #pragma unroll 8
        for (int k8 = 0; k8 < 8; ++k8) {
            uint4 uwr = __ldg(&W[k8 * 768 + j]);
            uint4 uwz = __ldg(&W[k8 * 768 + 256 + j]);
            uint4 uwn = __ldg(&W[k8 * 768 + 512 + j]);
            const __half2* hr = (const __half2*)&uwr;
            const __half2* hz = (const __half2*)&uwz;
            const __half2* hn = (const __half2*)&uwn;
            #pragma unroll
            for (int q = 0; q < 4; ++q) {
                float2 wr2 = __half22float2(hr[q]);
                float2 wz2 = __half22float2(hz[q]);
                float2 wn2 = __half22float2(hn[q]);
                float4 ia = *(const float4*)&s_in[k8 * 8 + 2 * q][0];
                float4 ib = *(const float4*)&s_in[k8 * 8 + 2 * q + 1][0];
                float2 a01 = make_float2(ia.x, ia.y), a23 = make_float2(ia.z, ia.w);
                float2 b01 = make_float2(ib.x, ib.y), b23 = make_float2(ib.z, ib.w);
                ffma2(ar0, dup2(wr2.x), a01); ffma2(ar1, dup2(wr2.x), a23);
                ffma2(az0, dup2(wz2.x), a01); ffma2(az1, dup2(wz2.x), a23);
                ffma2(ai0, dup2(wn2.x), a01); ffma2(ai1, dup2(wn2.x), a23);
                ffma2(ar0, dup2(wr2.y), b01); ffma2(ar1, dup2(wr2.y), b23);
                ffma2(az0, dup2(wz2.y), b01); ffma2(az1, dup2(wz2.y), b23);
                ffma2(ai0, dup2(wn2.y), b01); ffma2(ai1, dup2(wn2.y), b23);
            }
        }
    }
    {   // gh: k8 0..31 over s_h
        const uint4* W = (const uint4*)g_WHH;
        #pragma unroll 8
        for (int k8 = 0; k8 < 32; ++k8) {
            uint4 uwr = __ldg(&W[k8 * 768 + j]);
            uint4 uwz = __ldg(&W[k8 * 768 + 256 + j]);
            uint4 uwn = __ldg(&W[k8 * 768 + 512 + j]);
            const __half2* hr = (const __half2*)&uwr;
            const __half2* hz = (const __half2*)&uwz;
            const __half2* hn = (const __half2*)&uwn;
            #pragma unroll
            for (int q = 0; q < 4; ++q) {
                float2 wr2 = __half22float2(hr[q]);
                float2 wz2 = __half22float2(hz[q]);
                float2 wn2 = __half22float2(hn[q]);
                float4 ia = *(const float4*)&s_h[k8 * 8 + 2 * q][0];
                float4 ib = *(const float4*)&s_h[k8 * 8 + 2 * q + 1][0];
                float2 a01 = make_float2(ia.x, ia.y), a23 = make_float2(ia.z, ia.w);
                float2 b01 = make_float2(ib.x, ib.y), b23 = make_float2(ib.z, ib.w);
                ffma2(ar0, dup2(wr2.x), a01); ffma2(ar1, dup2(wr2.x), a23);
                ffma2(az0, dup2(wz2.x), a01); ffma2(az1, dup2(wz2.x), a23);
                ffma2(ah0, dup2(wn2.x), a01); ffma2(ah1, dup2(wn2.x), a23);
                ffma2(ar0, dup2(wr2.y), b01); ffma2(ar1, dup2(wr2.y), b23);
                ffma2(az0, dup2(wz2.y), b01); ffma2(az1, dup2(wz2.y), b23);
                ffma2(ah0, dup2(wn2.y), b01); ffma2(ah1, dup2(wn2.y), b23);
            }
        }
    }
    s_redB[0][j] = ar0.x;  s_redB[1][j] = ar0.y;  s_redB[2][j] = ar1.x;  s_redB[3][j] = ar1.y;
    s_redB[4][j] = az0.x;  s_redB[5][j] = az0.y;  s_redB[6][j] = az1.x;  s_redB[7][j] = az1.y;
    s_redB[8][j] = ai0.x;  s_redB[9][j] = ai0.y;  s_redB[10][j] = ai1.x; s_redB[11][j] = ai1.y;
    s_redB[12][j] = ah0.x; s_redB[13][j] = ah0.y; s_redB[14][j] = ah1.x; s_redB[15][j] = ah1.y;
}

// ---------------- K1: persistent pipelined kernel ----------------
__global__ __launch_bounds__(512, 1)
void ntm_main(const float* __restrict__ data, const int* __restrict__ batch_sizes,
              const int* __restrict__ unsort_idxs,
              const float* __restrict__ b_ih, const float* __restrict__ b_hh,
              const float* __restrict__ b_key, const float* __restrict__ b_beta,
              const float* __restrict__ b_erase, const float* __restrict__ b_add,
              const float* __restrict__ M0, float* __restrict__ out) {
    __shared__ __align__(16) float s_in[GINN][4];     // rows 0-63: x_{t+1}; rows 64-191: read
    __shared__ __align__(16) float s_h[CTRLN][4];
    __shared__ __align__(16) float s_redA[12][256];   // serial gi_read sk=1 partials
    __shared__ __align__(16) float s_redB[16][256];   // pipelined gh+gi_x partials
    __shared__ __align__(16) float s_key[4][WORDN];   // raw (tanh) key
    __shared__ __align__(16) float s_e[4][WORDN];
    __shared__ __align__(16) float s_a[4][WORDN];
    __shared__ __align__(16) float s_w[4][MEMN];
    __shared__ __align__(16) float s_racc[4][2][WORDN];
    __shared__ float s_beta[4];
    __shared__ int s_len[4];
    __shared__ int s_dst[4];

    const int tid = threadIdx.x;
    const int lane = tid & 31;
    const int warp = tid >> 5;
    const int b0 = blockIdx.x * 4;
    const int j = tid & 255;
    const int sk = tid >> 8;     // 0 = MEM warps (0-7), 1 = GEMV warps (8-15)

    // ---- active lengths ----
    if (warp < 4) {
        int e = warp, cnt = 0;
        for (int t = lane; t < TN; t += 32) cnt += (batch_sizes[t] > (b0 + e)) ? 1 : 0;
        #pragma unroll
        for (int s = 16; s; s >>= 1) cnt += __shfl_xor_sync(0xffffffffu, cnt, s);
        if (lane == 0) s_len[e] = cnt;
    }
    // ---- init M (fp16) from M0 ----
    for (int i = tid; i < (MEMN * WORDN) / 2; i += 512) {
        float2 f = ((const float2*)M0)[i];
        __half2 h = __floats2half2_rn(f.x, f.y);
        #pragma unroll
        for (int e = 0; e < 4; e++)
            ((__half2*)g_Mh)[(size_t)(b0 + e) * ((MEMN * WORDN) / 2) + i] = h;
    }
    for (int i = tid; i < GINN * 4; i += 512) (&s_in[0][0])[i] = 0.0f;
    for (int i = tid; i < CTRLN * 4; i += 512) (&s_h[0][0])[i] = 0.0f;

    // ---- biases ----
    float bR = 0.f, bZ = 0.f, bNi = 0.f, bNh = 0.f;   // GEMV warps
    if (sk == 1) {
        bR = b_ih[j] + b_hh[j];
        bZ = b_ih[256 + j] + b_hh[256 + j];
        bNi = b_ih[512 + j];
        bNh = b_hh[512 + j];
    }
    float bH1 = 0.f, bH2 = 0.f;                       // MEM warps (head outputs tid, 256+tid)
    if (sk == 0) {
        bH1 = (tid < 128) ? b_key[tid] : b_erase[tid - 128];
        bH2 = (tid < 128) ? b_add[tid] : ((tid == 128) ? b_beta[0] : 0.0f);
    }

    // ---- x prefetch prologue ----
    const int xe = tid >> 6, xd = tid & 63;           // valid for tid<256
    float xreg = 0.f;
    if (tid < 256) xreg = data[((size_t)0 * BN + (b0 + xe)) * DINN + xd];   // x_0
    __syncthreads();

    const int L0 = s_len[0], L1 = s_len[1], L2 = s_len[2], L3 = s_len[3];
    const int Tmax = max(max(L0, L1), max(L2, L3));

    if (tid < 256) {
        s_in[xd][xe] = xreg;                                                // x_0 -> smem
        xreg = data[((size_t)1 * BN + (b0 + xe)) * DINN + xd];              // x_1 -> reg
    }
    __syncthreads();
    // prologue pipelined GEMV: P_0 = gh(h=0) + gi_x(x_0) + biases
    if (sk == 1) gemv_P(j, bR, bZ, bNi, bNh, s_in, s_h, s_redB);
    __syncthreads();

    for (int t = 0; t < Tmax; ++t) {
        // ============ SERIAL: gi_read (K=128, rows 64-191), split-K 2 ways ============
        float2 gr0 = make_float2(0.f, 0.f), gr1 = make_float2(0.f, 0.f);
        float2 gz0 = make_float2(0.f, 0.f), gz1 = make_float2(0.f, 0.f);
        float2 gi0 = make_float2(0.f, 0.f), gi1 = make_float2(0.f, 0.f);
        {
            const uint4* W = (const uint4*)g_WIH;
            #pragma unroll 8
            for (int k8 = 8 + sk * 8; k8 < 16 + sk * 8; ++k8) {
                uint4 uwr = __ldg(&W[k8 * 768 + j]);
                uint4 uwz = __ldg(&W[k8 * 768 + 256 + j]);
                uint4 uwn = __ldg(&W[k8 * 768 + 512 + j]);
                const __half2* hr = (const __half2*)&uwr;
                const __half2* hz = (const __half2*)&uwz;
                const __half2* hn = (const __half2*)&uwn;
                #pragma unroll
                for (int q = 0; q < 4; ++q) {
                    float2 wr2 = __half22float2(hr[q]);
                    float2 wz2 = __half22float2(hz[q]);
                    float2 wn2 = __half22float2(hn[q]);
                    float4 ia = *(const float4*)&s_in[k8 * 8 + 2 * q][0];
                    float4 ib = *(const float4*)&s_in[k8 * 8 + 2 * q + 1][0];
                    float2 a01 = make_float2(ia.x, ia.y), a23 = make_float2(ia.z, ia.w);
                    float2 b01 = make_float2(ib.x, ib.y), b23 = make_float2(ib.z, ib.w);
                    ffma2(gr0, dup2(wr2.x), a01); ffma2(gr1, dup2(wr2.x), a23);
                    ffma2(gz0, dup2(wz2.x), a01); ffma2(gz1, dup2(wz2.x), a23);
                    ffma2(gi0, dup2(wn2.x), a01); ffma2(gi1, dup2(wn2.x), a23);
                    ffma2(gr0, dup2(wr2.y), b01); ffma2(gr1, dup2(wr2.y), b23);
                    ffma2(gz0, dup2(wz2.y), b01); ffma2(gz1, dup2(wz2.y), b23);
                    ffma2(gi0, dup2(wn2.y), b01); ffma2(gi1, dup2(wn2.y), b23);
                }
            }
        }
        if (sk == 1) {
            s_redA[0][j] = gr0.x;  s_redA[1][j] = gr0.y;  s_redA[2][j] = gr1.x;  s_redA[3][j] = gr1.y;
            s_redA[4][j] = gz0.x;  s_redA[5][j] = gz0.y;  s_redA[6][j] = gz1.x;  s_redA[7][j] = gz1.y;
            s_redA[8][j] = gi0.x;  s_redA[9][j] = gi0.y;  s_redA[10][j] = gi1.x; s_redA[11][j] = gi1.y;
        }
        __syncthreads();   // B1

        // ---- combine + gates (MEM warps) ----
        if (sk == 0) {
            float pr[4] = {gr0.x, gr0.y, gr1.x, gr1.y};
            float pz[4] = {gz0.x, gz0.y, gz1.x, gz1.y};
            float pi[4] = {gi0.x, gi0.y, gi1.x, gi1.y};
            float4 hold = *(const float4*)&s_h[j][0];
            float ho[4] = {hold.x, hold.y, hold.z, hold.w};
            float hn_[4];
            #pragma unroll
            for (int e = 0; e < 4; e++) {
                float ppr = pr[e] + s_redA[e][j] + s_redB[e][j];
                float ppz = pz[e] + s_redA[4 + e][j] + s_redB[4 + e][j];
                float ppi = pi[e] + s_redA[8 + e][j] + s_redB[8 + e][j];
                float pph = s_redB[12 + e][j];
                float r = sigf(ppr);
                float z = sigf(ppz);
                float n = tanhf(ppi + r * pph);
                hn_[e] = (1.0f - z) * n + z * ho[e];
            }
            if (t < L0) s_h[j][0] = hn_[0];
            if (t < L1) s_h[j][1] = hn_[1];
            if (t < L2) s_h[j][2] = hn_[2];
            if (t < L3) s_h[j][3] = hn_[3];
        }
        __syncthreads();   // B2: h_t ready

        // ---- store x_{t+1}, prefetch x_{t+2} ----
        if (tid < 256) {
            s_in[xd][xe] = xreg;
            int tn = min(t + 2, TN - 1);
            xreg = data[((size_t)tn * BN + (b0 + xe)) * DINN + xd];
        }
        __syncthreads();   // B3: fork

        // ============ PARALLEL SEGMENT ============
        if (sk == 1) {
            // GEMV warps: P_{t+1} = gh(h_t) + gi_x(x_{t+1}) + biases
            gemv_P(j, bR, bZ, bNi, bNh, s_in, s_h, s_redB);
        } else {
            // ---- MEM warps: head GEMV (outputs tid, 256+tid; K=256) ----
            float2 h10 = dup2(bH1), h11 = dup2(bH1);
            float2 h20 = dup2(bH2), h21 = dup2(bH2);
            {
                const uint4* W = (const uint4*)g_WHD;
                #pragma unroll 8
                for (int k8 = 0; k8 < 32; ++k8) {
                    uint4 uw1 = __ldg(&W[k8 * 512 + tid]);
                    uint4 uw2 = __ldg(&W[k8 * 512 + 256 + tid]);
                    const __half2* h1p = (const __half2*)&uw1;
                    const __half2* h2p = (const __half2*)&uw2;
                    #pragma unroll
                    for (int q = 0; q < 4; ++q) {
                        float2 w12 = __half22float2(h1p[q]);
                        float2 w22 = __half22float2(h2p[q]);
                        float4 ia = *(const float4*)&s_h[k8 * 8 + 2 * q][0];
                        float4 ib = *(const float4*)&s_h[k8 * 8 + 2 * q + 1][0];
                        float2 a01 = make_float2(ia.x, ia.y), a23 = make_float2(ia.z, ia.w);
                        float2 b01 = make_float2(ib.x, ib.y), b23 = make_float2(ib.z, ib.w);
                        ffma2(h10, dup2(w12.x), a01); ffma2(h11, dup2(w12.x), a23);
                        ffma2(h20, dup2(w22.x), a01); ffma2(h21, dup2(w22.x), a23);
                        ffma2(h10, dup2(w12.y), b01); ffma2(h11, dup2(w12.y), b23);
                        ffma2(h20, dup2(w22.y), b01); ffma2(h21, dup2(w22.y), b23);
                    }
                }
            }
            {
                float v1[4] = {h10.x, h10.y, h11.x, h11.y};
                float v2[4] = {h20.x, h20.y, h21.x, h21.y};
                #pragma unroll
                for (int e = 0; e < 4; e++) {
                    if (tid < 128) {
                        s_key[e][tid] = tanhf(v1[e]);   // raw key
                        s_a[e][tid] = v2[e];
                    } else {
                        s_e[e][tid - 128] = sigf(v1[e]);
                        if (tid == 128) s_beta[e] = softplusf(v2[e]);
                    }
                }
            }
            BARN(5, 256);   // all head outputs visible to all MEM warps

            const int e = warp >> 1, half = warp & 1;
            const int Le = s_len[e];
            if (t < Le) {
                // ---- pass 1: dot(M, k_raw)/(||M||+eps) ----
                const __half* Me = g_Mh + (size_t)(b0 + e) * (MEMN * WORDN);
                {
                    int rl = lane >> 3;
                    int cc = (lane & 7) * 16;
                    float kf[16];
                    #pragma unroll
                    for (int i = 0; i < 16; i++) kf[i] = s_key[e][cc + i];
                    #pragma unroll 4
                    for (int mb = half * 64; mb < half * 64 + 64; mb += 4) {
                        int m = mb + rl;
                        const uint4* Mr = (const uint4*)(Me + m * WORDN + cc);
                        uint4 u0 = __ldg(&Mr[0]);
                        uint4 u1 = __ldg(&Mr[1]);
                        const __half2* p0 = (const __half2*)&u0;
                        const __half2* p1 = (const __half2*)&u1;
                        float dot = 0.f, nrm = 0.f;
                        #pragma unroll
                        for (int q = 0; q < 4; q++) {
                            float2 f0 = __half22float2(p0[q]);
                            float2 f1 = __half22float2(p1[q]);
                            dot = fmaf(f0.x, kf[2 * q], dot);
                            dot = fmaf(f0.y, kf[2 * q + 1], dot);
                            dot = fmaf(f1.x, kf[8 + 2 * q], dot);
                            dot = fmaf(f1.y, kf[8 + 2 * q + 1], dot);
                            nrm = fmaf(f0.x, f0.x, nrm);
                            nrm = fmaf(f0.y, f0.y, nrm);
                            nrm = fmaf(f1.x, f1.x, nrm);
                            nrm = fmaf(f1.y, f1.y, nrm);
                        }
                        #pragma unroll
                        for (int s = 1; s < 8; s <<= 1) {
                            dot += __shfl_xor_sync(0xffffffffu, dot, s);
                            nrm += __shfl_xor_sync(0xffffffffu, nrm, s);
                        }
                        if ((lane & 7) == 0) s_w[e][m] = dot / (sqrtf(nrm) + EPSF);
                    }
                }
                BARN(1 + e, 64);
                // ---- softmax (half==0 warp): scale = beta / (||k||+eps) ----
                if (half == 0) {
                    float q0 = s_key[e][lane];
                    float q1 = s_key[e][lane + 32];
                    float q2 = s_key[e][lane + 64];
                    float q3 = s_key[e][lane + 96];
                    float ss = q0 * q0 + q1 * q1 + q2 * q2 + q3 * q3;
                    #pragma unroll
                    for (int s = 16; s; s >>= 1) ss += __shfl_xor_sync(0xffffffffu, ss, s);
                    float scale = s_beta[e] / (sqrtf(ss) + EPSF);
                    float v0 = scale * s_w[e][lane];
                    float v1 = scale * s_w[e][lane + 32];
                    float v2 = scale * s_w[e][lane + 64];
                    float v3 = scale * s_w[e][lane + 96];
                    float mx = fmaxf(fmaxf(v0, v1), fmaxf(v2, v3));
                    #pragma unroll
                    for (int s = 16; s; s >>= 1) mx = fmaxf(mx, __shfl_xor_sync(0xffffffffu, mx, s));
                    v0 = __expf(v0 - mx); v1 = __expf(v1 - mx);
                    v2 = __expf(v2 - mx); v3 = __expf(v3 - mx);
                    float sum = v0 + v1 + v2 + v3;
                    #pragma unroll
                    for (int s = 16; s; s >>= 1) sum += __shfl_xor_sync(0xffffffffu, sum, s);
                    float inv = 1.0f / sum;
                    s_w[e][lane] = v0 * inv;
                    s_w[e][lane + 32] = v1 * inv;
                    s_w[e][lane + 64] = v2 * inv;
                    s_w[e][lane + 96] = v3 * inv;
                }
                BARN(1 + e, 64);
                // ---- pass 2: read + M update ----
                {
                    __half* Mw = g_Mh + (size_t)(b0 + e) * (MEMN * WORDN);
                    float4 e4 = *(const float4*)&s_e[e][lane * 4];
                    float4 a4 = *(const float4*)&s_a[e][lane * 4];
                    float4 racc = make_float4(0.f, 0.f, 0.f, 0.f);
                    #pragma unroll 8
                    for (int m = half * 64; m < half * 64 + 64; ++m) {
                        float wm = s_w[e][m];
                        uint2* Mr = (uint2*)(Mw + m * WORDN + lane * 4);
                        uint2 u = *Mr;
                        __half2* hp = (__half2*)&u;
                        float2 m01 = __half22float2(hp[0]);
                        float2 m23 = __half22float2(hp[1]);
                        racc.x = fmaf(wm, m01.x, racc.x);
                        racc.y = fmaf(wm, m01.y, racc.y);
                        racc.z = fmaf(wm, m23.x, racc.z);
                        racc.w = fmaf(wm, m23.y, racc.w);
                        float f0 = fmaf(-wm, e4.x, 1.0f);
                        float f1 = fmaf(-wm, e4.y, 1.0f);
                        float f2 = fmaf(-wm, e4.z, 1.0f);
                        float f3 = fmaf(-wm, e4.w, 1.0f);
                        float n0 = fmaf(m01.x, f0, wm * a4.x);
                        float n1 = fmaf(m01.y, f1, wm * a4.y);
                        float n2 = fmaf(m23.x, f2, wm * a4.z);
                        float n3 = fmaf(m23.y, f3, wm * a4.w);
                        hp[0] = __floats2half2_rn(n0, n1);
                        hp[1] = __floats2half2_rn(n2, n3);
                        *Mr = u;
                    }
                    *(float4*)&s_racc[e][half][lane * 4] = racc;
                }
                BARN(1 + e, 64);
                // ---- combine read halves -> s_in rows 64.. ----
                {
                    int w = half * 32 + lane;
                    s_in[64 + w][e] = s_racc[e][0][w] + s_racc[e][1][w];
                    int w2 = w + 64;
                    s_in[64 + w2][e] = s_racc[e][0][w2] + s_racc[e][1][w2];
                }
            }
        }
        __syncthreads();   // B4: join
    }

    // ---- epilogue ----
    for (int q = tid; q < BN; q += 512) {
        int u = unsort_idxs[q];
        if (u >= b0 && u < b0 + 4) s_dst[u - b0] = q;
    }
    __syncthreads();
    if (tid < 256) {
        #pragma unroll
        for (int e = 0; e < 4; e++)
            out[(size_t)s_dst[e] * CTRLN + tid] = s_h[tid][e];
    }
    {
        int e = tid >> 7, w = tid & 127;
        out[(size_t)BN * CTRLN + (size_t)s_dst[e] * WORDN + w] = s_in[64 + w][e];
    }
}

// ---------------- launch ----------------
extern "C" void kernel_launch(void* const* d_in, const int* in_sizes, int n_in,
                              void* d_out, int out_size) {
    const float* data        = (const float*)d_in[0];
    const int*   batch_sizes = (const int*)d_in[1];
    const int*   unsort      = (const int*)d_in[2];
    const float* W_ih        = (const float*)d_in[3];
    const float* b_ih        = (const float*)d_in[4];
    const float* W_hh        = (const float*)d_in[5];
    const float* b_hh        = (const float*)d_in[6];
    const float* W_key       = (const float*)d_in[7];
    const float* b_key       = (const float*)d_in[8];
    const float* W_beta      = (const float*)d_in[9];
    const float* b_beta      = (const float*)d_in[10];
    const float* W_erase     = (const float*)d_in[11];
    const float* b_erase     = (const float*)d_in[12];
    const float* W_add       = (const float*)d_in[13];
    const float* b_add       = (const float*)d_in[14];
    const float* M0          = (const float*)d_in[15];

    ntm_prep<<<256, 256>>>(W_ih, W_hh, W_key, W_beta, W_erase, W_add);
    ntm_main<<<128, 512>>>(data, batch_sizes, unsort,
                           b_ih, b_hh, b_key, b_beta, b_erase, b_add,
                           M0, (float*)d_out);
}